// round 15
// baseline (speedup 1.0000x reference)
#include <cuda_runtime.h>

// Collapsed math: out[b,c] = softmax_c( d*r/1000 + d + r ),
// r = x[b,0,c], d = x[b,1,c]; logits in [0, 2.001] -> no max pass needed.
// exp computed in log2 domain: e = exp2( (d*r)*(1e-3*log2e) + (d+r)*log2e ).
//
// CTA-per-row (32 threads, grid 65536) + 256-bit global accesses:
//   - ld/st.global.cs.v8.f32 (32B/lane, 1024B/warp-request; bases 32B-aligned)
//   - all 4 load iterations unconditional (tail lanes clamp to idx 124 and
//     load a duplicate in-bounds vector; accumulate/store stay predicated)
//   - warp-only shfl reduction; no smem, no __syncthreads

#define NUM_CLASSES 1000
#define V8_PER_ROW (NUM_CLASSES / 8)       // 125 float8 per row per tensor
#define ROW_F_STRIDE (2 * NUM_CLASSES)     // 2000 floats per (2,1000) row
#define THREADS 32
#define FULL_ITERS 3                       // lane + 32*2 = 95 < 125 always
#define LOG2E 1.4426950408889634f

__device__ __forceinline__ void ldg256_cs(const float* p, float* v)
{
    asm("ld.global.cs.v8.f32 {%0,%1,%2,%3,%4,%5,%6,%7}, [%8];"
        : "=f"(v[0]), "=f"(v[1]), "=f"(v[2]), "=f"(v[3]),
          "=f"(v[4]), "=f"(v[5]), "=f"(v[6]), "=f"(v[7])
        : "l"(p));
}

__device__ __forceinline__ void stg256_cs(float* p, const float* v)
{
    asm volatile("st.global.cs.v8.f32 [%0], {%1,%2,%3,%4,%5,%6,%7,%8};"
        :: "l"(p),
           "f"(v[0]), "f"(v[1]), "f"(v[2]), "f"(v[3]),
           "f"(v[4]), "f"(v[5]), "f"(v[6]), "f"(v[7])
        : "memory");
}

__global__ __launch_bounds__(THREADS) void tmc_softmax_v8(
    const float* __restrict__ x, float* __restrict__ out)
{
    const int lane = threadIdx.x;
    const size_t row = blockIdx.x;

    const float* __restrict__ rgb = x + row * ROW_F_STRIDE;
    const float* __restrict__ dep = rgb + NUM_CLASSES;
    float* __restrict__ outp = out + row * NUM_CLASSES;

    const bool tail = (lane + 32 * FULL_ITERS) < V8_PER_ROW;   // lane < 29
    const int tidx8 = (tail ? (lane + 32 * FULL_ITERS) : (V8_PER_ROW - 1)) * 8;

    float ev[(FULL_ITERS + 1) * 8];
    float local = 0.f;

    // All loads unconditional (tail lanes fetch a duplicate in-bounds vector).
    float r[4][8], d[4][8];
    #pragma unroll
    for (int i = 0; i < FULL_ITERS; i++) {
        const int idx = (lane + 32 * i) * 8;
        ldg256_cs(rgb + idx, r[i]);
        ldg256_cs(dep + idx, d[i]);
    }
    ldg256_cs(rgb + tidx8, r[FULL_ITERS]);
    ldg256_cs(dep + tidx8, d[FULL_ITERS]);

    #pragma unroll
    for (int i = 0; i < FULL_ITERS; i++) {
        #pragma unroll
        for (int j = 0; j < 8; j++) {
            float e = exp2f(fmaf(d[i][j] * r[i][j], 1e-3f * LOG2E,
                                 (d[i][j] + r[i][j]) * LOG2E));
            ev[i * 8 + j] = e;
            local += e;
        }
    }
    if (tail) {
        #pragma unroll
        for (int j = 0; j < 8; j++) {
            float e = exp2f(fmaf(d[FULL_ITERS][j] * r[FULL_ITERS][j], 1e-3f * LOG2E,
                                 (d[FULL_ITERS][j] + r[FULL_ITERS][j]) * LOG2E));
            ev[FULL_ITERS * 8 + j] = e;
            local += e;
        }
    }

    // Warp-only reduction: no barriers, no smem.
    #pragma unroll
    for (int off = 16; off > 0; off >>= 1)
        local += __shfl_xor_sync(0xFFFFFFFFu, local, off);

    const float inv = 1.0f / local;

    #pragma unroll
    for (int i = 0; i < FULL_ITERS; i++) {
        const int idx = (lane + 32 * i) * 8;
        float o[8];
        #pragma unroll
        for (int j = 0; j < 8; j++) o[j] = ev[i * 8 + j] * inv;
        stg256_cs(outp + idx, o);
    }
    if (tail) {
        float o[8];
        #pragma unroll
        for (int j = 0; j < 8; j++) o[j] = ev[FULL_ITERS * 8 + j] * inv;
        stg256_cs(outp + tidx8, o);
    }
}

extern "C" void kernel_launch(void* const* d_in, const int* in_sizes, int n_in,
                              void* d_out, int out_size)
{
    const float* x = (const float*)d_in[0];
    float* out = (float*)d_out;
    const int batch = in_sizes[0] / ROW_F_STRIDE;   // 65536
    tmc_softmax_v8<<<batch, THREADS>>>(x, out);
}